// round 6
// baseline (speedup 1.0000x reference)
#include <cuda_runtime.h>
#include <cooperative_groups.h>

namespace cg = cooperative_groups;

#define CS   8
#define TPB  256

// ---- shared memory layout (float offsets) ----
// shared weights
static constexpr int OFF_WHS  = 0;       // 2 * 32*129 = 8256 : Whs[bb][q][h] pad129
static constexpr int OFF_WGT  = 8256;    // 256*33 = 8448     : WgT[k][j] pad33 (staging q/p)
static constexpr int OFF_WIHK = 16704;   // 32*520 = 16640    : WihT_k[k][j] (my 32 x-cols, 512 outs)
static constexpr int OFF_WHHK = 33344;   // 16*520 = 8320     : WhhT_k[k][j] (my 16 h-cols)
static constexpr int OFF_WRK  = 41664;   // 16*132 = 2112     : WrT_k[k][j]  (my 16 h-cols, 128 outs)
static constexpr int OFF_WE   = 43776;   // 128
static constexpr int OFF_WRB  = 43904;   // 128
static constexpr int OFF_WGB  = 44032;   // 32
static constexpr int OFF_BIHH = 44064;   // 64
static constexpr int OFF_ST   = 44128;   // per-batch state below
// per-batch state (relative), stride SBS
static constexpr int P_U    = 0;      // 128
static constexpr int P_X    = 128;    // 256 : [alpha, p_t]
static constexpr int P_PQ   = 384;    // 32
static constexpr int P_XM   = 416;    // 32  : gated x slice (local)
static constexpr int P_HM   = 448;    // 16  : my h slice
static constexpr int P_C    = 464;    // 16
static constexpr int P_PART = 480;    // 256
static constexpr int P_ACB  = 736;    // 8*128 : softmax acc per-rank (pushed)
static constexpr int P_LB   = 1760;   // 8
static constexpr int P_UACB = 1768;   // 8*128 : u partials per-rank (pushed)
static constexpr int P_GIH  = 2792;   // 8*64  : Wih gate partials (pushed)
static constexpr int P_GHH  = 3304;   // 2*8*64: Whh gate partials, parity buffered (pushed)
static constexpr int SBS    = 4336;
static constexpr int SMEM_FLOATS = OFF_ST + 2 * SBS;   // 52800 floats = 211200 B

__device__ float g_wtp[16 * 128 * 128];   // wt_pre scratch [B][P][H]

__device__ __forceinline__ float fast_tanh(float x) {
    float y; asm("tanh.approx.f32 %0, %1;" : "=f"(y) : "f"(x)); return y;
}
__device__ __forceinline__ float sigm(float x) {
    return __fdividef(1.f, 1.f + __expf(-x));
}
__device__ __forceinline__ float tanh_ex(float x) {
    float e = __expf(2.f * x);
    return 1.f - __fdividef(2.f, e + 1.f);
}
__device__ __forceinline__ float warp_sum(float v) {
    #pragma unroll
    for (int o = 16; o; o >>= 1) v += __shfl_xor_sync(0xffffffffu, v, o);
    return v;
}
__device__ __forceinline__ void dsmem_st(const float* localp, int r, float v) {
    uint32_t l = (uint32_t)__cvta_generic_to_shared(localp), rm;
    asm("mapa.shared::cluster.u32 %0, %1, %2;" : "=r"(rm) : "r"(l), "r"(r));
    asm volatile("st.shared::cluster.f32 [%0], %1;" :: "r"(rm), "f"(v) : "memory");
}
__device__ __forceinline__ void csync() {
    asm volatile("barrier.cluster.arrive.aligned;" ::: "memory");
    asm volatile("barrier.cluster.wait.aligned;" ::: "memory");
}

__global__ void __launch_bounds__(TPB, 1) __cluster_dims__(CS, 1, 1)
mlstm_kernel(const float* __restrict__ p_in,  const float* __restrict__ q_in,
             const float* __restrict__ Ws_w,  const float* __restrict__ Ws_b,
             const float* __restrict__ Wt_w,  const float* __restrict__ Wt_b,
             const float* __restrict__ Wr_w,  const float* __restrict__ Wr_b,
             const float* __restrict__ We_w,
             const float* __restrict__ Wg_w,  const float* __restrict__ Wg_b,
             const float* __restrict__ Wih,   const float* __restrict__ Whh,
             const float* __restrict__ bih,   const float* __restrict__ bhh,
             float* __restrict__ out)
{
    extern __shared__ float s[];
    cg::cluster_group cl = cg::this_cluster();
    const int rank = (int)cl.block_rank();
    const int b0   = (int)(blockIdx.x >> 3) * 2;   // 2 batches per cluster
    const int tid  = (int)threadIdx.x;
    const int lane = tid & 31;
    const int warp = tid >> 5;

    // ============================ PROLOGUE ============================
    // P1: Whs[bb] = q(32 rows) @ Ws^T + b   (Ws staged pad132 at OFF_WIHK, q at OFF_WGT)
    for (int i4 = tid; i4 < 4096; i4 += TPB) {
        int hh = i4 >> 5, k = i4 & 31;
        *(float4*)&s[OFF_WIHK + hh * 132 + k * 4] = ((const float4*)Ws_w)[i4];
    }
    #pragma unroll
    for (int bb = 0; bb < 2; bb++)
        for (int i4 = tid; i4 < 1024; i4 += TPB)
            ((float4*)&s[OFF_WGT + bb * 4096])[i4] =
                ((const float4*)(q_in + (size_t)((b0 + bb) * 256 + rank * 32) * 128))[i4];
    __syncthreads();
    #pragma unroll
    for (int bb = 0; bb < 2; bb++) {
        int hh = tid & 127, q0 = (tid >> 7) * 16;
        const float4* wrow = (const float4*)&s[OFF_WIHK + hh * 132];
        float acc[16];
        float sb = Ws_b[hh];
        #pragma unroll
        for (int i = 0; i < 16; i++) acc[i] = sb;
        for (int k = 0; k < 32; k++) {
            float4 w = wrow[k];
            #pragma unroll
            for (int i = 0; i < 16; i++) {
                float4 qv = *(const float4*)&s[OFF_WGT + bb * 4096 + (q0 + i) * 128 + k * 4];
                acc[i] += w.x * qv.x + w.y * qv.y + w.z * qv.z + w.w * qv.w;
            }
        }
        #pragma unroll
        for (int i = 0; i < 16; i++) s[OFF_WHS + bb * 4128 + (q0 + i) * 129 + hh] = acc[i];
    }
    __syncthreads();

    // P2: wt_pre[bb] = p(16 rows) @ Wt^T + b -> gmem scratch
    for (int i4 = tid; i4 < 4096; i4 += TPB) {
        int hh = i4 >> 5, k = i4 & 31;
        *(float4*)&s[OFF_WIHK + hh * 132 + k * 4] = ((const float4*)Wt_w)[i4];
    }
    #pragma unroll
    for (int bb = 0; bb < 2; bb++)
        for (int i4 = tid; i4 < 512; i4 += TPB)
            ((float4*)&s[OFF_WGT + bb * 2048])[i4] =
                ((const float4*)(p_in + (size_t)((b0 + bb) * 128 + rank * 16) * 128))[i4];
    __syncthreads();
    #pragma unroll
    for (int bb = 0; bb < 2; bb++) {
        int hh = tid & 127, t0 = (tid >> 7) * 8;
        const float4* wrow = (const float4*)&s[OFF_WIHK + hh * 132];
        float acc[8];
        float bt = Wt_b[hh];
        #pragma unroll
        for (int i = 0; i < 8; i++) acc[i] = bt;
        for (int k = 0; k < 32; k++) {
            float4 w = wrow[k];
            #pragma unroll
            for (int i = 0; i < 8; i++) {
                float4 pv = *(const float4*)&s[OFF_WGT + bb * 2048 + (t0 + i) * 128 + k * 4];
                acc[i] += w.x * pv.x + w.y * pv.y + w.z * pv.z + w.w * pv.w;
            }
        }
        #pragma unroll
        for (int i = 0; i < 8; i++)
            g_wtp[(size_t)((b0 + bb) * 128 + rank * 16 + t0 + i) * 128 + hh] = acc[i];
    }
    __syncthreads();

    // P3: final weights (k-partitioned)
    for (int idx = tid; idx < 512 * 32; idx += TPB) {   // WihT_k: cols rank*32..+31
        int j = idx >> 5, kk = idx & 31;
        s[OFF_WIHK + kk * 520 + j] = Wih[(size_t)j * 256 + rank * 32 + kk];
    }
    for (int idx = tid; idx < 512 * 16; idx += TPB) {   // WhhT_k: cols rank*16..+15
        int j = idx >> 4, kk = idx & 15;
        s[OFF_WHHK + kk * 520 + j] = Whh[(size_t)j * 128 + rank * 16 + kk];
    }
    for (int idx = tid; idx < 128 * 16; idx += TPB) {   // WrT_k
        int j = idx >> 4, kk = idx & 15;
        s[OFF_WRK + kk * 132 + j] = Wr_w[(size_t)j * 128 + rank * 16 + kk];
    }
    for (int idx = tid; idx < 8192; idx += TPB) {       // WgT pad33 (my 32 j-rows)
        int j = idx >> 8, k = idx & 255;
        s[OFF_WGT + k * 33 + j] = Wg_w[(size_t)(rank * 32 + j) * 256 + k];
    }
    if (tid < 128) { s[OFF_WE + tid] = We_w[tid]; s[OFF_WRB + tid] = Wr_b[tid]; }
    if (tid < 32) s[OFF_WGB + tid] = Wg_b[rank * 32 + tid];
    if (tid < 64) {
        int grow = (tid >> 4) * 128 + rank * 16 + (tid & 15);
        s[OFF_BIHH + tid] = bih[grow] + bhh[grow];
    }
    #pragma unroll
    for (int bb = 0; bb < 2; bb++) {
        int S = OFF_ST + bb * SBS;
        for (int i = tid; i < 1024; i += TPB) { s[S + P_UACB + i] = 0.f; s[S + P_GHH + i] = 0.f; }
        if (tid < 16) s[S + P_C + tid] = 0.f;
    }
    __threadfence();     // g_wtp visible cluster-wide
    __syncthreads();
    csync();

    // ============================ MAIN LOOP ============================
    for (int t = 0; t < 128; t++) {
        const int par = t & 1;

        // ---- A: u = wtp + b + sum_r u-partials ; load p_t ----
        {
            int bb = tid >> 7, j = tid & 127;
            int S = OFF_ST + bb * SBS;
            float pv = p_in[(size_t)((b0 + bb) * 128 + t) * 128 + j];
            float wv = g_wtp[(size_t)((b0 + bb) * 128 + t) * 128 + j];
            float u = wv + s[OFF_WRB + j];
            #pragma unroll
            for (int r = 0; r < 8; r++) u += s[S + P_UACB + r * 128 + j];
            s[S + P_U + j] = u;
            s[S + P_X + 128 + j] = pv;
        }
        __syncthreads();   // S1

        // ---- B: scores (warp -> 8 q's of one batch) ----
        {
            int bb = warp >> 2;
            int S  = OFF_ST + bb * SBS;
            int q0 = (warp & 3) * 8;
            const float* whs = &s[OFF_WHS + bb * 4128];
            float a0=0.f,a1=0.f,a2=0.f,a3=0.f,a4=0.f,a5=0.f,a6=0.f,a7=0.f;
            #pragma unroll
            for (int c = 0; c < 4; c++) {
                int h = c * 32 + lane;
                float uh = s[S + P_U + h], we = s[OFF_WE + h];
                a0 += fast_tanh(whs[(q0 + 0) * 129 + h] + uh) * we;
                a1 += fast_tanh(whs[(q0 + 1) * 129 + h] + uh) * we;
                a2 += fast_tanh(whs[(q0 + 2) * 129 + h] + uh) * we;
                a3 += fast_tanh(whs[(q0 + 3) * 129 + h] + uh) * we;
                a4 += fast_tanh(whs[(q0 + 4) * 129 + h] + uh) * we;
                a5 += fast_tanh(whs[(q0 + 5) * 129 + h] + uh) * we;
                a6 += fast_tanh(whs[(q0 + 6) * 129 + h] + uh) * we;
                a7 += fast_tanh(whs[(q0 + 7) * 129 + h] + uh) * we;
            }
            a0=warp_sum(a0); a1=warp_sum(a1); a2=warp_sum(a2); a3=warp_sum(a3);
            a4=warp_sum(a4); a5=warp_sum(a5); a6=warp_sum(a6); a7=warp_sum(a7);
            if (lane == 0) {   // no-max softmax: |score| <= ||We||_1 ~ 5
                s[S + P_PQ + q0 + 0] = __expf(a0);
                s[S + P_PQ + q0 + 1] = __expf(a1);
                s[S + P_PQ + q0 + 2] = __expf(a2);
                s[S + P_PQ + q0 + 3] = __expf(a3);
                s[S + P_PQ + q0 + 4] = __expf(a4);
                s[S + P_PQ + q0 + 5] = __expf(a5);
                s[S + P_PQ + q0 + 6] = __expf(a6);
                s[S + P_PQ + q0 + 7] = __expf(a7);
            }
        }
        __syncthreads();   // S2

        // ---- push softmax partial acc + l ----
        if (tid < 128) {
            #pragma unroll
            for (int bb = 0; bb < 2; bb++) {
                int S = OFF_ST + bb * SBS;
                float a = 0.f;
                #pragma unroll
                for (int q = 0; q < 32; q++)
                    a += s[S + P_PQ + q] * s[OFF_WHS + bb * 4128 + q * 129 + tid];
                const float* dst = &s[S + P_ACB + rank * 128 + tid];
                #pragma unroll
                for (int r = 0; r < 8; r++) dsmem_st(dst, r, a);
            }
        } else if (warp == 4 || warp == 5) {
            int bb = warp - 4;
            int S = OFF_ST + bb * SBS;
            float l = warp_sum(s[S + P_PQ + lane]);
            if (lane == 0) {
                const float* dst = &s[S + P_LB + rank];
                #pragma unroll
                for (int r = 0; r < 8; r++) dsmem_st(dst, r, l);
            }
        }
        csync();           // C1

        // ---- C: alpha ----
        if (tid < 128) {
            #pragma unroll
            for (int bb = 0; bb < 2; bb++) {
                int S = OFF_ST + bb * SBS;
                float a = 0.f, L = 0.f;
                #pragma unroll
                for (int r = 0; r < 8; r++) {
                    a += s[S + P_ACB + r * 128 + tid];
                    L += s[S + P_LB + r];
                }
                s[S + P_X + tid] = __fdividef(a, L);
            }
        }
        __syncthreads();   // S3

        // ---- D: input-gate partials ----
        #pragma unroll
        for (int bb = 0; bb < 2; bb++) {
            int S = OFF_ST + bb * SBS;
            float pp = 0.f;
            #pragma unroll 8
            for (int kk = 0; kk < 32; kk++) {
                int k = warp * 32 + kk;
                pp += s[OFF_WGT + k * 33 + lane] * s[S + P_X + k];
            }
            s[S + P_PART + warp * 32 + lane] = pp;
        }
        __syncthreads();   // S4
        if (tid < 64) {
            int bb = tid >> 5, j = tid & 31;
            int S = OFF_ST + bb * SBS;
            float sum = 0.f;
            #pragma unroll
            for (int w = 0; w < 8; w++) sum += s[S + P_PART + w * 32 + j];
            float g = sigm(sum + s[OFF_WGB + j]);
            s[S + P_XM + j] = g * s[S + P_X + rank * 32 + j];
        }
        __syncthreads();   // S5

        // ---- Dfin: Wih k-partial gates, push to owners ----
        #pragma unroll
        for (int bb = 0; bb < 2; bb++) {
            int S = OFF_ST + bb * SBS;
            #pragma unroll
            for (int m = 0; m < 2; m++) {
                int j = tid + m * 256;
                float pg = 0.f;
                #pragma unroll 8
                for (int k = 0; k < 32; k++)
                    pg += s[OFF_WIHK + k * 520 + j] * s[S + P_XM + k];
                int o = (j & 127) >> 4, slot = (j >> 7) * 16 + (j & 15);
                dsmem_st(&s[S + P_GIH + rank * 64 + slot], o, pg);
            }
        }
        csync();           // C2

        // ---- F: gates, pointwise, h; then u/Whh partial pushes ----
        if (tid < 32) {
            int bb = tid >> 4, ss = tid & 15;
            int S = OFF_ST + bb * SBS;
            float g[4];
            #pragma unroll
            for (int gt = 0; gt < 4; gt++) {
                float v = s[OFF_BIHH + gt * 16 + ss];
                #pragma unroll
                for (int r = 0; r < 8; r++) {
                    v += s[S + P_GIH + r * 64 + gt * 16 + ss];
                    v += s[S + P_GHH + par * 512 + r * 64 + gt * 16 + ss];
                }
                g[gt] = v;
            }
            float cn = sigm(g[1]) * s[S + P_C + ss] + sigm(g[0]) * tanh_ex(g[2]);
            float hn = sigm(g[3]) * tanh_ex(cn);
            s[S + P_C + ss]  = cn;
            s[S + P_HM + ss] = hn;
            out[(size_t)((b0 + bb) * 128 + t) * 128 + rank * 16 + ss] = hn;
        }
        __syncthreads();   // S6
        {
            int bb = tid >> 7, j = tid & 127;
            int S = OFF_ST + bb * SBS;
            float pu = 0.f;
            #pragma unroll
            for (int k = 0; k < 16; k++)
                pu += s[OFF_WRK + k * 132 + j] * s[S + P_HM + k];
            const float* dst = &s[S + P_UACB + rank * 128 + j];
            #pragma unroll
            for (int r = 0; r < 8; r++) dsmem_st(dst, r, pu);
            int o = j >> 4, jl = j & 15;
            #pragma unroll
            for (int m = 0; m < 4; m++) {
                int jj = j + m * 128;
                float pg = 0.f;
                #pragma unroll
                for (int k = 0; k < 16; k++)
                    pg += s[OFF_WHHK + k * 520 + jj] * s[S + P_HM + k];
                dsmem_st(&s[S + P_GHH + (par ^ 1) * 512 + rank * 64 + m * 16 + jl], o, pg);
            }
        }
        csync();           // C3
    }

    csync();
}

extern "C" void kernel_launch(void* const* d_in, const int* in_sizes, int n_in,
                              void* d_out, int out_size) {
    (void)in_sizes; (void)n_in; (void)out_size;
    cudaFuncSetAttribute(mlstm_kernel, cudaFuncAttributeMaxDynamicSharedMemorySize,
                         SMEM_FLOATS * (int)sizeof(float));
    mlstm_kernel<<<64, TPB, SMEM_FLOATS * sizeof(float)>>>(
        (const float*)d_in[0],  (const float*)d_in[1],
        (const float*)d_in[2],  (const float*)d_in[3],
        (const float*)d_in[4],  (const float*)d_in[5],
        (const float*)d_in[6],  (const float*)d_in[7],
        (const float*)d_in[8],
        (const float*)d_in[10], (const float*)d_in[11],
        (const float*)d_in[12], (const float*)d_in[13],
        (const float*)d_in[14], (const float*)d_in[15],
        (float*)d_out);
}

// round 7
// speedup vs baseline: 1.8503x; 1.8503x over previous
#include <cuda_runtime.h>
#include <cooperative_groups.h>

namespace cg = cooperative_groups;

#define CS   8
#define TPB  256

// ---- shared memory layout (float offsets) ----
static constexpr int OFF_WHS  = 0;       // 2*32*129 = 8256 : Whs[bb][q][h] pad129
static constexpr int OFF_WGT  = 8256;    // 256*33 = 8448   : WgT[k][j] pad33 (staging q/p)
static constexpr int OFF_WIHK = 16704;   // 32*520 = 16640  : WihT_k[k][j] (staging Ws/Wt pad132, overruns into WHHK scratch-safe)
static constexpr int OFF_WHHK = 33344;   // 16*520 = 8320   : WhhT_k[k][j]
static constexpr int OFF_WRK  = 41664;   // 16*132 = 2112   : WrT_k[k][j]
static constexpr int OFF_WE   = 43776;   // 128
static constexpr int OFF_WRB  = 43904;   // 128
static constexpr int OFF_WGB  = 44032;   // 32
static constexpr int OFF_BIHH = 44064;   // 64
static constexpr int OFF_MBAR = 44128;   // 16 floats = 8 u64 slots (6 used)
static constexpr int OFF_ST   = 44144;
// per-batch state, stride SBS
static constexpr int P_U    = 0;      // 128
static constexpr int P_X    = 128;    // 256 : [alpha, p_t]
static constexpr int P_PQ   = 384;    // 32
static constexpr int P_XM   = 416;    // 32
static constexpr int P_HM   = 448;    // 16
static constexpr int P_C    = 464;    // 16
static constexpr int P_ACB  = 480;    // 8*128 (pushed)
static constexpr int P_LB   = 1504;   // 8     (pushed)
static constexpr int P_UACB = 1512;   // 8*128 (pushed)
static constexpr int P_GIH  = 2536;   // 8*64  (pushed)
static constexpr int P_GHH  = 3048;   // 2*8*64 parity buffered (pushed)
static constexpr int SBS    = 4072;
static constexpr int SMEM_FLOATS = OFF_ST + 2 * SBS;   // 52288 floats = 209152 B

// mbar byte offsets: i=0 hpart, 1 acc, 2 gih
__device__ __forceinline__ uint32_t MBB(int bb, int i) {
    return (uint32_t)(OFF_MBAR * 4 + (bb * 3 + i) * 8);
}

__device__ float g_wtp[16 * 128 * 128];   // wt_pre scratch [B][P][H]

__device__ __forceinline__ float fast_tanh(float x) {
    float y; asm("tanh.approx.f32 %0, %1;" : "=f"(y) : "f"(x)); return y;
}
__device__ __forceinline__ float sigm(float x) {
    return __fdividef(1.f, 1.f + __expf(-x));
}
__device__ __forceinline__ float tanh_ex(float x) {
    float e = __expf(2.f * x);
    return 1.f - __fdividef(2.f, e + 1.f);
}
__device__ __forceinline__ float warp_sum(float v) {
    #pragma unroll
    for (int o = 16; o; o >>= 1) v += __shfl_xor_sync(0xffffffffu, v, o);
    return v;
}
__device__ __forceinline__ uint32_t mapa_rank(uint32_t base, int r) {
    uint32_t rm;
    asm("mapa.shared::cluster.u32 %0, %1, %2;" : "=r"(rm) : "r"(base), "r"(r));
    return rm;
}
// data + completion: remote shared store signaling remote mbarrier tx
__device__ __forceinline__ void st_async(uint32_t rbase, int foff, uint32_t mb_byte, float v) {
    asm volatile("st.async.shared::cluster.mbarrier::complete_tx::bytes.b32 [%0], %1, [%2];"
                 :: "r"(rbase + (uint32_t)foff * 4u), "r"(__float_as_uint(v)),
                    "r"(rbase + mb_byte) : "memory");
}
__device__ __forceinline__ void mbar_init(uint32_t addr) {
    asm volatile("mbarrier.init.shared.b64 [%0], 1;" :: "r"(addr) : "memory");
}
__device__ __forceinline__ void mbar_expect(uint32_t addr, uint32_t bytes) {
    asm volatile("mbarrier.arrive.expect_tx.shared.b64 _, [%0], %1;" :: "r"(addr), "r"(bytes) : "memory");
}
__device__ __forceinline__ void mbar_wait(uint32_t addr, uint32_t parity) {
    asm volatile(
        "{\n\t.reg .pred P1;\n\t"
        "WL%=:\n\t"
        "mbarrier.try_wait.parity.acquire.cluster.shared::cta.b64 P1, [%0], %1, 0x989680;\n\t"
        "@P1 bra.uni WD%=;\n\t"
        "bra.uni WL%=;\n\t"
        "WD%=:\n\t}"
        :: "r"(addr), "r"(parity) : "memory");
}
__device__ __forceinline__ void barg(int bb) {
    asm volatile("bar.sync %0, 128;" :: "r"(1 + bb) : "memory");
}
__device__ __forceinline__ void csync() {
    asm volatile("barrier.cluster.arrive.aligned;" ::: "memory");
    asm volatile("barrier.cluster.wait.aligned;" ::: "memory");
}

__global__ void __launch_bounds__(TPB, 1) __cluster_dims__(CS, 1, 1)
mlstm_kernel(const float* __restrict__ p_in,  const float* __restrict__ q_in,
             const float* __restrict__ Ws_w,  const float* __restrict__ Ws_b,
             const float* __restrict__ Wt_w,  const float* __restrict__ Wt_b,
             const float* __restrict__ Wr_w,  const float* __restrict__ Wr_b,
             const float* __restrict__ We_w,
             const float* __restrict__ Wg_w,  const float* __restrict__ Wg_b,
             const float* __restrict__ Wih,   const float* __restrict__ Whh,
             const float* __restrict__ bih,   const float* __restrict__ bhh,
             float* __restrict__ out)
{
    extern __shared__ float s[];
    cg::cluster_group cl = cg::this_cluster();
    const int rank = (int)cl.block_rank();
    const int b0   = (int)(blockIdx.x >> 3) * 2;
    const int tid  = (int)threadIdx.x;
    const int lane = tid & 31;

    // ============================ PROLOGUE ============================
    // P1: Whs[bb] = q(32 rows) @ Ws^T + b   (Ws staged pad132 at OFF_WIHK, q at OFF_WGT)
    for (int i4 = tid; i4 < 4096; i4 += TPB) {
        int hh = i4 >> 5, k = i4 & 31;
        *(float4*)&s[OFF_WIHK + hh * 132 + k * 4] = ((const float4*)Ws_w)[i4];
    }
    #pragma unroll
    for (int bb = 0; bb < 2; bb++)
        for (int i4 = tid; i4 < 1024; i4 += TPB)
            ((float4*)&s[OFF_WGT + bb * 4096])[i4] =
                ((const float4*)(q_in + (size_t)((b0 + bb) * 256 + rank * 32) * 128))[i4];
    __syncthreads();
    #pragma unroll
    for (int bb = 0; bb < 2; bb++) {
        int hh = tid & 127, q0 = (tid >> 7) * 16;
        const float4* wrow = (const float4*)&s[OFF_WIHK + hh * 132];
        float acc[16];
        float sb = Ws_b[hh];
        #pragma unroll
        for (int i = 0; i < 16; i++) acc[i] = sb;
        for (int k = 0; k < 32; k++) {
            float4 w = wrow[k];
            #pragma unroll
            for (int i = 0; i < 16; i++) {
                float4 qv = *(const float4*)&s[OFF_WGT + bb * 4096 + (q0 + i) * 128 + k * 4];
                acc[i] += w.x * qv.x + w.y * qv.y + w.z * qv.z + w.w * qv.w;
            }
        }
        #pragma unroll
        for (int i = 0; i < 16; i++) s[OFF_WHS + bb * 4128 + (q0 + i) * 129 + hh] = acc[i];
    }
    __syncthreads();

    // P2: wt_pre[bb] = p(16 rows) @ Wt^T + b -> gmem scratch
    for (int i4 = tid; i4 < 4096; i4 += TPB) {
        int hh = i4 >> 5, k = i4 & 31;
        *(float4*)&s[OFF_WIHK + hh * 132 + k * 4] = ((const float4*)Wt_w)[i4];
    }
    #pragma unroll
    for (int bb = 0; bb < 2; bb++)
        for (int i4 = tid; i4 < 512; i4 += TPB)
            ((float4*)&s[OFF_WGT + bb * 2048])[i4] =
                ((const float4*)(p_in + (size_t)((b0 + bb) * 128 + rank * 16) * 128))[i4];
    __syncthreads();
    #pragma unroll
    for (int bb = 0; bb < 2; bb++) {
        int hh = tid & 127, t0 = (tid >> 7) * 8;
        const float4* wrow = (const float4*)&s[OFF_WIHK + hh * 132];
        float acc[8];
        float bt = Wt_b[hh];
        #pragma unroll
        for (int i = 0; i < 8; i++) acc[i] = bt;
        for (int k = 0; k < 32; k++) {
            float4 w = wrow[k];
            #pragma unroll
            for (int i = 0; i < 8; i++) {
                float4 pv = *(const float4*)&s[OFF_WGT + bb * 2048 + (t0 + i) * 128 + k * 4];
                acc[i] += w.x * pv.x + w.y * pv.y + w.z * pv.z + w.w * pv.w;
            }
        }
        #pragma unroll
        for (int i = 0; i < 8; i++)
            g_wtp[(size_t)((b0 + bb) * 128 + rank * 16 + t0 + i) * 128 + hh] = acc[i];
    }
    __syncthreads();

    // P3: resident weights (k-partitioned)
    for (int idx = tid; idx < 512 * 32; idx += TPB) {
        int j = idx >> 5, kk = idx & 31;
        s[OFF_WIHK + kk * 520 + j] = Wih[(size_t)j * 256 + rank * 32 + kk];
    }
    for (int idx = tid; idx < 512 * 16; idx += TPB) {
        int j = idx >> 4, kk = idx & 15;
        s[OFF_WHHK + kk * 520 + j] = Whh[(size_t)j * 128 + rank * 16 + kk];
    }
    for (int idx = tid; idx < 128 * 16; idx += TPB) {
        int j = idx >> 4, kk = idx & 15;
        s[OFF_WRK + kk * 132 + j] = Wr_w[(size_t)j * 128 + rank * 16 + kk];
    }
    for (int idx = tid; idx < 8192; idx += TPB) {
        int j = idx >> 8, k = idx & 255;
        s[OFF_WGT + k * 33 + j] = Wg_w[(size_t)(rank * 32 + j) * 256 + k];
    }
    if (tid < 128) { s[OFF_WE + tid] = We_w[tid]; s[OFF_WRB + tid] = Wr_b[tid]; }
    if (tid < 32) s[OFF_WGB + tid] = Wg_b[rank * 32 + tid];
    if (tid < 64) {
        int grow = (tid >> 4) * 128 + rank * 16 + (tid & 15);
        s[OFF_BIHH + tid] = bih[grow] + bhh[grow];
    }
    #pragma unroll
    for (int bbz = 0; bbz < 2; bbz++) {
        int S = OFF_ST + bbz * SBS;
        for (int i = tid; i < 1024; i += TPB) { s[S + P_UACB + i] = 0.f; s[S + P_GHH + i] = 0.f; }
        if (tid < 16) s[S + P_C + tid] = 0.f;
    }
    const uint32_t sbase = (uint32_t)__cvta_generic_to_shared(s);
    if (tid == 0) {
        #pragma unroll
        for (int bbz = 0; bbz < 2; bbz++)
            #pragma unroll
            for (int i = 0; i < 3; i++) mbar_init(sbase + MBB(bbz, i));
        asm volatile("fence.mbarrier_init.release.cluster;" ::: "memory");
        // prologue expects for phase 0 of acc / gih (hpart armed at top of step 0)
        #pragma unroll
        for (int bbz = 0; bbz < 2; bbz++) {
            mbar_expect(sbase + MBB(bbz, 1), 4128u);
            mbar_expect(sbase + MBB(bbz, 2), 2048u);
        }
    }
    __threadfence();     // g_wtp visible cluster-wide
    __syncthreads();
    csync();

    // ============================ MAIN LOOP (warp-split batches) ============================
    const int bb = tid >> 7;          // warps 0-3 -> batch 0, warps 4-7 -> batch 1
    const int wg = tid & 127;
    const int gwarp = wg >> 5;
    const int S  = OFF_ST + bb * SBS;
    const int gb = b0 + bb;
    uint32_t rb[CS];
    #pragma unroll
    for (int r = 0; r < CS; r++) rb[r] = mapa_rank(sbase, r);
    const uint32_t rbo = rb[0] + (mapa_rank(sbase, wg >> 4) - rb[0]); // owner base (runtime rank)
    const uint32_t mb_hp = sbase + MBB(bb, 0);
    const uint32_t mb_ac = sbase + MBB(bb, 1);
    const uint32_t mb_gi = sbase + MBB(bb, 2);
    const uint32_t MB_HP = MBB(bb, 0), MB_AC = MBB(bb, 1), MB_GI = MBB(bb, 2);

    float wtp_r = g_wtp[(size_t)(gb * 128) * 128 + wg];
    float p_r   = p_in[(size_t)(gb * 128) * 128 + wg];

    for (int t = 0; t < 128; t++) {
        // ---- A: wait h-partials; u ----
        if (t) mbar_wait(mb_hp, (t - 1) & 1);
        if (wg == 0) mbar_expect(mb_hp, 6144u);
        {
            float u = wtp_r + s[OFF_WRB + wg];
            #pragma unroll
            for (int r = 0; r < CS; r++) u += s[S + P_UACB + r * 128 + wg];
            s[S + P_U + wg] = u;
            s[S + P_X + 128 + wg] = p_r;
        }
        barg(bb);

        // ---- B: scores (gwarp -> 8 q's) ----
        {
            int q0 = gwarp * 8;
            const float* whs = &s[OFF_WHS + bb * 4128];
            float a[8] = {0.f, 0.f, 0.f, 0.f, 0.f, 0.f, 0.f, 0.f};
            #pragma unroll
            for (int c = 0; c < 4; c++) {
                int h = c * 32 + lane;
                float uh = s[S + P_U + h], we = s[OFF_WE + h];
                #pragma unroll
                for (int i = 0; i < 8; i++)
                    a[i] += fast_tanh(whs[(q0 + i) * 129 + h] + uh) * we;
            }
            #pragma unroll
            for (int i = 0; i < 8; i++) a[i] = warp_sum(a[i]);
            if (lane == 0) {
                #pragma unroll
                for (int i = 0; i < 8; i++) s[S + P_PQ + q0 + i] = __expf(a[i]);
            }
        }
        barg(bb);

        // ---- push acc + l ----
        {
            float a = 0.f;
            #pragma unroll
            for (int q = 0; q < 32; q++)
                a += s[S + P_PQ + q] * s[OFF_WHS + bb * 4128 + q * 129 + wg];
            #pragma unroll
            for (int r = 0; r < CS; r++)
                st_async(rb[r], S + P_ACB + rank * 128 + wg, MB_AC, a);
            if (gwarp == 0) {
                float l = warp_sum(s[S + P_PQ + lane]);
                if (lane == 0) {
                    #pragma unroll
                    for (int r = 0; r < CS; r++)
                        st_async(rb[r], S + P_LB + rank, MB_AC, l);
                }
            }
        }

        // ---- C: wait acc; alpha ----
        mbar_wait(mb_ac, t & 1);
        if (wg == 0) mbar_expect(mb_ac, 4128u);
        {
            float a = 0.f, L = 0.f;
            #pragma unroll
            for (int r = 0; r < CS; r++) {
                a += s[S + P_ACB + r * 128 + wg];
                L += s[S + P_LB + r];
            }
            s[S + P_X + wg] = __fdividef(a, L);
        }
        barg(bb);

        // ---- D: input gate (gwarp -> 8 j's, full 256-dot) ----
        {
            int j0 = gwarp * 8;
            float a[8] = {0.f, 0.f, 0.f, 0.f, 0.f, 0.f, 0.f, 0.f};
            #pragma unroll
            for (int c = 0; c < 8; c++) {
                int k = c * 32 + lane;
                float xv = s[S + P_X + k];
                #pragma unroll
                for (int i = 0; i < 8; i++)
                    a[i] += s[OFF_WGT + k * 33 + j0 + i] * xv;
            }
            #pragma unroll
            for (int i = 0; i < 8; i++) a[i] = warp_sum(a[i]);
            if (lane == 0) {
                #pragma unroll
                for (int i = 0; i < 8; i++) {
                    float g = sigm(a[i] + s[OFF_WGB + j0 + i]);
                    s[S + P_XM + j0 + i] = g * s[S + P_X + rank * 32 + j0 + i];
                }
            }
        }
        barg(bb);

        // ---- Dfin: Wih k-partial gates -> owners ----
        #pragma unroll
        for (int m = 0; m < 4; m++) {
            int j = wg + m * 128;
            float pg = 0.f;
            #pragma unroll
            for (int k = 0; k < 32; k++)
                pg += s[OFF_WIHK + k * 520 + j] * s[S + P_XM + k];
            st_async(rbo, S + P_GIH + rank * 64 + m * 16 + (wg & 15), MB_GI, pg);
        }

        // prefetch next step's wtp / p
        {
            int tn = (t < 127) ? t + 1 : 127;
            wtp_r = g_wtp[(size_t)(gb * 128 + tn) * 128 + wg];
            p_r   = p_in[(size_t)(gb * 128 + tn) * 128 + wg];
        }

        // ---- F: wait gate partials; pointwise; push h-partials ----
        mbar_wait(mb_gi, t & 1);
        if (wg == 0) mbar_expect(mb_gi, 2048u);
        if (wg < 16) {
            float g[4];
            #pragma unroll
            for (int gt = 0; gt < 4; gt++) {
                float v = s[OFF_BIHH + gt * 16 + wg];
                #pragma unroll
                for (int r = 0; r < CS; r++) {
                    v += s[S + P_GIH + r * 64 + gt * 16 + wg];
                    v += s[S + P_GHH + (t & 1) * 512 + r * 64 + gt * 16 + wg];
                }
                g[gt] = v;
            }
            float cn = sigm(g[1]) * s[S + P_C + wg] + sigm(g[0]) * tanh_ex(g[2]);
            float hn = sigm(g[3]) * tanh_ex(cn);
            s[S + P_C + wg]  = cn;
            s[S + P_HM + wg] = hn;
            out[(size_t)(gb * 128 + t) * 128 + rank * 16 + wg] = hn;
        }
        barg(bb);
        if (t < 127) {
            float pu = 0.f;
            #pragma unroll
            for (int k = 0; k < 16; k++)
                pu += s[OFF_WRK + k * 132 + wg] * s[S + P_HM + k];
            #pragma unroll
            for (int r = 0; r < CS; r++)
                st_async(rb[r], S + P_UACB + rank * 128 + wg, MB_HP, pu);
            #pragma unroll
            for (int m = 0; m < 4; m++) {
                int jj = wg + m * 128;
                float pg = 0.f;
                #pragma unroll
                for (int k = 0; k < 16; k++)
                    pg += s[OFF_WHHK + k * 520 + jj] * s[S + P_HM + k];
                st_async(rbo, S + P_GHH + ((t + 1) & 1) * 512 + rank * 64 + m * 16 + (wg & 15),
                         MB_HP, pg);
            }
        }
    }

    csync();   // no CTA exits while peers may still target its SMEM
}

extern "C" void kernel_launch(void* const* d_in, const int* in_sizes, int n_in,
                              void* d_out, int out_size) {
    (void)in_sizes; (void)n_in; (void)out_size;
    cudaFuncSetAttribute(mlstm_kernel, cudaFuncAttributeMaxDynamicSharedMemorySize,
                         SMEM_FLOATS * (int)sizeof(float));
    mlstm_kernel<<<64, TPB, SMEM_FLOATS * sizeof(float)>>>(
        (const float*)d_in[0],  (const float*)d_in[1],
        (const float*)d_in[2],  (const float*)d_in[3],
        (const float*)d_in[4],  (const float*)d_in[5],
        (const float*)d_in[6],  (const float*)d_in[7],
        (const float*)d_in[8],
        (const float*)d_in[10], (const float*)d_in[11],
        (const float*)d_in[12], (const float*)d_in[13],
        (const float*)d_in[14], (const float*)d_in[15],
        (float*)d_out);
}

// round 8
// speedup vs baseline: 1.9902x; 1.0756x over previous
#include <cuda_runtime.h>
#include <cooperative_groups.h>

namespace cg = cooperative_groups;

#define CS   8
#define TPB  512

// ---- shared memory layout (float offsets) ----
static constexpr int OFF_WHS  = 0;       // 2*32*129 = 8256 : Whs[bb][q][h] pad129
static constexpr int OFF_WGT  = 8256;    // 256*33 = 8448   : WgT[k][j] pad33 (staging q/p)
static constexpr int OFF_WIHK = 16704;   // 32*520 = 16640  : WihT_k[k][j] (staging Ws/Wt pad132; overruns into WHHK scratch-safe)
static constexpr int OFF_WHHK = 33344;   // 16*520 = 8320   : WhhT_k[k][j]
static constexpr int OFF_WRK  = 41664;   // 16*132 = 2112   : WrT_k[k][j]
static constexpr int OFF_WE   = 43776;   // 128
static constexpr int OFF_WRB  = 43904;   // 128
static constexpr int OFF_WGB  = 44032;   // 32
static constexpr int OFF_BIHH = 44064;   // 64
static constexpr int OFF_MBAR = 44128;   // 16 floats = 8 u64 slots (6 used)
static constexpr int OFF_ST   = 44144;
// per-batch state, stride SBS
static constexpr int P_U    = 0;      // 128
static constexpr int P_X    = 128;    // 256 : [alpha, p_t]
static constexpr int P_PQ   = 384;    // 32
static constexpr int P_XM   = 416;    // 32
static constexpr int P_HM   = 448;    // 16
static constexpr int P_C    = 464;    // 16
static constexpr int P_ACB  = 480;    // 8*128 (pushed)
static constexpr int P_LB   = 1504;   // 8     (pushed)
static constexpr int P_UACB = 1512;   // 8*128 (pushed)
static constexpr int P_GIH  = 2536;   // 8*64  (pushed)
static constexpr int P_GHH  = 3048;   // 2*8*64 parity buffered (pushed)
static constexpr int SBS    = 4072;
static constexpr int SMEM_FLOATS = OFF_ST + 2 * SBS;   // 52288 floats = 209152 B

__device__ __forceinline__ uint32_t MBB(int bb, int i) {   // i: 0 hpart, 1 acc, 2 gih
    return (uint32_t)(OFF_MBAR * 4 + (bb * 3 + i) * 8);
}

__device__ float g_wtp[16 * 128 * 128];   // wt_pre scratch [B][P][H]

__device__ __forceinline__ float fast_tanh(float x) {
    float y; asm("tanh.approx.f32 %0, %1;" : "=f"(y) : "f"(x)); return y;
}
__device__ __forceinline__ float sigm(float x) {
    return __fdividef(1.f, 1.f + __expf(-x));
}
__device__ __forceinline__ float tanh_ex(float x) {
    float e = __expf(2.f * x);
    return 1.f - __fdividef(2.f, e + 1.f);
}
__device__ __forceinline__ float warp_sum(float v) {
    #pragma unroll
    for (int o = 16; o; o >>= 1) v += __shfl_xor_sync(0xffffffffu, v, o);
    return v;
}
__device__ __forceinline__ uint32_t mapa_rank(uint32_t base, int r) {
    uint32_t rm;
    asm("mapa.shared::cluster.u32 %0, %1, %2;" : "=r"(rm) : "r"(base), "r"(r));
    return rm;
}
__device__ __forceinline__ void st_async32(uint32_t rbase, int foff, uint32_t mb_byte, float v) {
    asm volatile("st.async.shared::cluster.mbarrier::complete_tx::bytes.b32 [%0], %1, [%2];"
                 :: "r"(rbase + (uint32_t)foff * 4u), "r"(__float_as_uint(v)),
                    "r"(rbase + mb_byte) : "memory");
}
__device__ __forceinline__ void st_async64(uint32_t rbase, int foff, uint32_t mb_byte,
                                           float a, float b) {
    uint64_t v = ((uint64_t)__float_as_uint(b) << 32) | (uint64_t)__float_as_uint(a);
    asm volatile("st.async.shared::cluster.mbarrier::complete_tx::bytes.b64 [%0], %1, [%2];"
                 :: "r"(rbase + (uint32_t)foff * 4u), "l"(v), "r"(rbase + mb_byte) : "memory");
}
__device__ __forceinline__ void mbar_init(uint32_t addr) {
    asm volatile("mbarrier.init.shared.b64 [%0], 1;" :: "r"(addr) : "memory");
}
__device__ __forceinline__ void mbar_expect(uint32_t addr, uint32_t bytes) {
    asm volatile("mbarrier.arrive.expect_tx.shared.b64 _, [%0], %1;" :: "r"(addr), "r"(bytes) : "memory");
}
__device__ __forceinline__ void mbar_wait(uint32_t addr, uint32_t parity) {
    asm volatile(
        "{\n\t.reg .pred P1;\n\t"
        "WL%=:\n\t"
        "mbarrier.try_wait.parity.acquire.cluster.shared::cta.b64 P1, [%0], %1, 0x989680;\n\t"
        "@P1 bra.uni WD%=;\n\t"
        "bra.uni WL%=;\n\t"
        "WD%=:\n\t}"
        :: "r"(addr), "r"(parity) : "memory");
}
__device__ __forceinline__ void barg(int bb) {
    asm volatile("bar.sync %0, 256;" :: "r"(1 + bb) : "memory");
}
__device__ __forceinline__ void csync() {
    asm volatile("barrier.cluster.arrive.aligned;" ::: "memory");
    asm volatile("barrier.cluster.wait.aligned;" ::: "memory");
}

__global__ void __launch_bounds__(TPB, 1) __cluster_dims__(CS, 1, 1)
mlstm_kernel(const float* __restrict__ p_in,  const float* __restrict__ q_in,
             const float* __restrict__ Ws_w,  const float* __restrict__ Ws_b,
             const float* __restrict__ Wt_w,  const float* __restrict__ Wt_b,
             const float* __restrict__ Wr_w,  const float* __restrict__ Wr_b,
             const float* __restrict__ We_w,
             const float* __restrict__ Wg_w,  const float* __restrict__ Wg_b,
             const float* __restrict__ Wih,   const float* __restrict__ Whh,
             const float* __restrict__ bih,   const float* __restrict__ bhh,
             float* __restrict__ out)
{
    extern __shared__ float s[];
    cg::cluster_group cl = cg::this_cluster();
    const int rank = (int)cl.block_rank();
    const int b0   = (int)(blockIdx.x >> 3) * 2;
    const int tid  = (int)threadIdx.x;
    const int lane = tid & 31;

    // ============================ PROLOGUE ============================
    // P1: Whs[bb] = q(32 rows) @ Ws^T + b  (Ws staged pad132 at OFF_WIHK, q at OFF_WGT)
    for (int i4 = tid; i4 < 4096; i4 += TPB) {
        int hh = i4 >> 5, k = i4 & 31;
        *(float4*)&s[OFF_WIHK + hh * 132 + k * 4] = ((const float4*)Ws_w)[i4];
    }
    #pragma unroll
    for (int bb = 0; bb < 2; bb++)
        for (int i4 = tid; i4 < 1024; i4 += TPB)
            ((float4*)&s[OFF_WGT + bb * 4096])[i4] =
                ((const float4*)(q_in + (size_t)((b0 + bb) * 256 + rank * 32) * 128))[i4];
    __syncthreads();
    #pragma unroll
    for (int bb = 0; bb < 2; bb++) {
        int hh = tid & 127, q0 = (tid >> 7) * 8;   // 4 groups of 8 q-rows
        const float4* wrow = (const float4*)&s[OFF_WIHK + hh * 132];
        float acc[8];
        float sb = Ws_b[hh];
        #pragma unroll
        for (int i = 0; i < 8; i++) acc[i] = sb;
        for (int k = 0; k < 32; k++) {
            float4 w = wrow[k];
            #pragma unroll
            for (int i = 0; i < 8; i++) {
                float4 qv = *(const float4*)&s[OFF_WGT + bb * 4096 + (q0 + i) * 128 + k * 4];
                acc[i] += w.x * qv.x + w.y * qv.y + w.z * qv.z + w.w * qv.w;
            }
        }
        #pragma unroll
        for (int i = 0; i < 8; i++) s[OFF_WHS + bb * 4128 + (q0 + i) * 129 + hh] = acc[i];
    }
    __syncthreads();

    // P2: wt_pre[bb] = p(16 rows) @ Wt^T + b -> gmem scratch
    for (int i4 = tid; i4 < 4096; i4 += TPB) {
        int hh = i4 >> 5, k = i4 & 31;
        *(float4*)&s[OFF_WIHK + hh * 132 + k * 4] = ((const float4*)Wt_w)[i4];
    }
    #pragma unroll
    for (int bb = 0; bb < 2; bb++)
        for (int i4 = tid; i4 < 512; i4 += TPB)
            ((float4*)&s[OFF_WGT + bb * 2048])[i4] =
                ((const float4*)(p_in + (size_t)((b0 + bb) * 128 + rank * 16) * 128))[i4];
    __syncthreads();
    #pragma unroll
    for (int bb = 0; bb < 2; bb++) {
        int hh = tid & 127, t0 = (tid >> 7) * 4;   // 4 groups of 4 rows
        const float4* wrow = (const float4*)&s[OFF_WIHK + hh * 132];
        float acc[4];
        float bt = Wt_b[hh];
        #pragma unroll
        for (int i = 0; i < 4; i++) acc[i] = bt;
        for (int k = 0; k < 32; k++) {
            float4 w = wrow[k];
            #pragma unroll
            for (int i = 0; i < 4; i++) {
                float4 pv = *(const float4*)&s[OFF_WGT + bb * 2048 + (t0 + i) * 128 + k * 4];
                acc[i] += w.x * pv.x + w.y * pv.y + w.z * pv.z + w.w * pv.w;
            }
        }
        #pragma unroll
        for (int i = 0; i < 4; i++)
            g_wtp[(size_t)((b0 + bb) * 128 + rank * 16 + t0 + i) * 128 + hh] = acc[i];
    }
    __syncthreads();

    // P3: resident weights (k-partitioned)
    for (int idx = tid; idx < 512 * 32; idx += TPB) {
        int j = idx >> 5, kk = idx & 31;
        s[OFF_WIHK + kk * 520 + j] = Wih[(size_t)j * 256 + rank * 32 + kk];
    }
    for (int idx = tid; idx < 512 * 16; idx += TPB) {
        int j = idx >> 4, kk = idx & 15;
        s[OFF_WHHK + kk * 520 + j] = Whh[(size_t)j * 128 + rank * 16 + kk];
    }
    for (int idx = tid; idx < 128 * 16; idx += TPB) {
        int j = idx >> 4, kk = idx & 15;
        s[OFF_WRK + kk * 132 + j] = Wr_w[(size_t)j * 128 + rank * 16 + kk];
    }
    for (int idx = tid; idx < 8192; idx += TPB) {
        int j = idx >> 8, k = idx & 255;
        s[OFF_WGT + k * 33 + j] = Wg_w[(size_t)(rank * 32 + j) * 256 + k];
    }
    if (tid < 128) { s[OFF_WE + tid] = We_w[tid]; s[OFF_WRB + tid] = Wr_b[tid]; }
    if (tid < 32) s[OFF_WGB + tid] = Wg_b[rank * 32 + tid];
    if (tid < 64) {
        int grow = (tid >> 4) * 128 + rank * 16 + (tid & 15);
        s[OFF_BIHH + tid] = bih[grow] + bhh[grow];
    }
    #pragma unroll
    for (int bbz = 0; bbz < 2; bbz++) {
        int S = OFF_ST + bbz * SBS;
        for (int i = tid; i < 1024; i += TPB) { s[S + P_UACB + i] = 0.f; s[S + P_GHH + i] = 0.f; }
        if (tid < 16) s[S + P_C + tid] = 0.f;
    }
    const uint32_t sbase = (uint32_t)__cvta_generic_to_shared(s);
    if (tid == 0) {
        #pragma unroll
        for (int bbz = 0; bbz < 2; bbz++)
            #pragma unroll
            for (int i = 0; i < 3; i++) mbar_init(sbase + MBB(bbz, i));
        asm volatile("fence.mbarrier_init.release.cluster;" ::: "memory");
        #pragma unroll
        for (int bbz = 0; bbz < 2; bbz++) {
            mbar_expect(sbase + MBB(bbz, 1), 4128u);
            mbar_expect(sbase + MBB(bbz, 2), 2048u);
        }
    }
    __threadfence();     // g_wtp visible cluster-wide
    __syncthreads();
    csync();

    // ==================== MAIN LOOP (warp-split batches, 8 warps each) ====================
    const int bb = tid >> 8;           // warps 0-7 -> batch0, 8-15 -> batch1
    const int wg = tid & 255;
    const int cw = wg >> 5;            // chain warp 0..7
    const int S  = OFF_ST + bb * SBS;
    const int gb = b0 + bb;
    uint32_t rb[CS];
    #pragma unroll
    for (int r = 0; r < CS; r++) rb[r] = mapa_rank(sbase, r);
    const uint32_t mb_hp = sbase + MBB(bb, 0);
    const uint32_t mb_ac = sbase + MBB(bb, 1);
    const uint32_t mb_gi = sbase + MBB(bb, 2);
    const uint32_t MB_HP = MBB(bb, 0), MB_AC = MBB(bb, 1), MB_GI = MBB(bb, 2);

    float wtp_r = 0.f, p_r = 0.f;
    if (wg < 128) {
        wtp_r = g_wtp[(size_t)(gb * 128) * 128 + wg];
        p_r   = p_in[(size_t)(gb * 128) * 128 + wg];
    }

    for (int t = 0; t < 128; t++) {
        // ---- A: wait h-partials; u ----
        if (t) mbar_wait(mb_hp, (t - 1) & 1);
        if (wg == 0) mbar_expect(mb_hp, 6144u);
        if (wg < 128) {
            float u = wtp_r + s[OFF_WRB + wg];
            #pragma unroll
            for (int r = 0; r < CS; r++) u += s[S + P_UACB + r * 128 + wg];
            s[S + P_U + wg] = u;
            s[S + P_X + 128 + wg] = p_r;
        }
        barg(bb);

        // ---- B: scores (cw -> 4 q's) ----
        {
            int q0 = cw * 4;
            const float* whs = &s[OFF_WHS + bb * 4128];
            float a[4] = {0.f, 0.f, 0.f, 0.f};
            #pragma unroll
            for (int c = 0; c < 4; c++) {
                int h = c * 32 + lane;
                float uh = s[S + P_U + h], we = s[OFF_WE + h];
                #pragma unroll
                for (int i = 0; i < 4; i++)
                    a[i] += fast_tanh(whs[(q0 + i) * 129 + h] + uh) * we;
            }
            #pragma unroll
            for (int i = 0; i < 4; i++) a[i] = warp_sum(a[i]);
            if (lane == 0) {   // no-max softmax: |score| <= ||We||_1 ~ 5
                #pragma unroll
                for (int i = 0; i < 4; i++) s[S + P_PQ + q0 + i] = __expf(a[i]);
            }
        }
        barg(bb);

        // ---- push acc (b64-paired) + l ----
        if (wg < 128) {
            float a = 0.f;
            #pragma unroll
            for (int q = 0; q < 32; q++)
                a += s[S + P_PQ + q] * s[OFF_WHS + bb * 4128 + q * 129 + wg];
            float an = __shfl_xor_sync(0xffffffffu, a, 1);
            if (!(wg & 1)) {
                #pragma unroll
                for (int r = 0; r < CS; r++)
                    st_async64(rb[r], S + P_ACB + rank * 128 + wg, MB_AC, a, an);
            }
        } else if (cw == 4) {
            float l = warp_sum(s[S + P_PQ + lane]);
            if (lane == 0) {
                #pragma unroll
                for (int r = 0; r < CS; r++)
                    st_async32(rb[r], S + P_LB + rank, MB_AC, l);
            }
        }

        // ---- C: wait acc; alpha ----
        mbar_wait(mb_ac, t & 1);
        if (wg == 0) mbar_expect(mb_ac, 4128u);
        if (wg < 128) {
            float a = 0.f, L = 0.f;
            #pragma unroll
            for (int r = 0; r < CS; r++) {
                a += s[S + P_ACB + r * 128 + wg];
                L += s[S + P_LB + r];
            }
            s[S + P_X + wg] = __fdividef(a, L);
        }
        barg(bb);

        // ---- D: input gate (cw -> 4 j's, full 256-dot) ----
        {
            int j0 = cw * 4;
            float a[4] = {0.f, 0.f, 0.f, 0.f};
            #pragma unroll
            for (int c = 0; c < 8; c++) {
                int k = c * 32 + lane;
                float xv = s[S + P_X + k];
                #pragma unroll
                for (int i = 0; i < 4; i++)
                    a[i] += s[OFF_WGT + k * 33 + j0 + i] * xv;
            }
            #pragma unroll
            for (int i = 0; i < 4; i++) a[i] = warp_sum(a[i]);
            if (lane == 0) {
                #pragma unroll
                for (int i = 0; i < 4; i++) {
                    float g = sigm(a[i] + s[OFF_WGB + j0 + i]);
                    s[S + P_XM + j0 + i] = g * s[S + P_X + rank * 32 + j0 + i];
                }
            }
        }
        barg(bb);

        // ---- Dfin: Wih k-partial gates (2 consecutive j per thread, b64 push) ----
        {
            int j = 2 * wg;                     // 0..510
            float a0 = 0.f, a1 = 0.f;
            #pragma unroll
            for (int k = 0; k < 32; k++) {
                float xm = s[S + P_XM + k];
                float2 w2 = *(const float2*)&s[OFF_WIHK + k * 520 + j];
                a0 += w2.x * xm; a1 += w2.y * xm;
            }
            int hh = j & 127;
            int owner = hh >> 4;
            int slot = (j >> 7) * 16 + (hh & 15);
            st_async64(rb[owner], S + P_GIH + rank * 64 + slot, MB_GI, a0, a1);
        }

        // prefetch next step's wtp / p
        if (wg < 128) {
            int tn = (t < 127) ? t + 1 : 127;
            wtp_r = g_wtp[(size_t)(gb * 128 + tn) * 128 + wg];
            p_r   = p_in[(size_t)(gb * 128 + tn) * 128 + wg];
        }

        // ---- F: wait gate partials; pointwise ----
        mbar_wait(mb_gi, t & 1);
        if (wg == 0) mbar_expect(mb_gi, 2048u);
        if (wg < 16) {
            float g[4];
            #pragma unroll
            for (int gt = 0; gt < 4; gt++) {
                float v = s[OFF_BIHH + gt * 16 + wg];
                #pragma unroll
                for (int r = 0; r < CS; r++) {
                    v += s[S + P_GIH + r * 64 + gt * 16 + wg];
                    v += s[S + P_GHH + (t & 1) * 512 + r * 64 + gt * 16 + wg];
                }
                g[gt] = v;
            }
            float cn = sigm(g[1]) * s[S + P_C + wg] + sigm(g[0]) * tanh_ex(g[2]);
            float hn = sigm(g[3]) * tanh_ex(cn);
            s[S + P_C + wg]  = cn;
            s[S + P_HM + wg] = hn;
            out[(size_t)(gb * 128 + t) * 128 + rank * 16 + wg] = hn;
        }
        barg(bb);

        // ---- push h-partials: u (Wr_k) + LSTM (Whh_k) ----
        if (t < 127) {
            if (wg < 128) {
                float pu = 0.f;
                #pragma unroll
                for (int k = 0; k < 16; k++)
                    pu += s[OFF_WRK + k * 132 + wg] * s[S + P_HM + k];
                float pn = __shfl_xor_sync(0xffffffffu, pu, 1);
                if (!(wg & 1)) {
                    #pragma unroll
                    for (int r = 0; r < CS; r++)
                        st_async64(rb[r], S + P_UACB + rank * 128 + wg, MB_HP, pu, pn);
                }
            }
            {
                int j = 2 * wg;
                float a0 = 0.f, a1 = 0.f;
                #pragma unroll
                for (int k = 0; k < 16; k++) {
                    float hv = s[S + P_HM + k];
                    float2 w2 = *(const float2*)&s[OFF_WHHK + k * 520 + j];
                    a0 += w2.x * hv; a1 += w2.y * hv;
                }
                int hh = j & 127;
                int owner = hh >> 4;
                int slot = (j >> 7) * 16 + (hh & 15);
                st_async64(rb[owner],
                           S + P_GHH + ((t + 1) & 1) * 512 + rank * 64 + slot, MB_HP, a0, a1);
            }
        }
    }

    csync();   // no CTA exits while peers may still target its SMEM
}

extern "C" void kernel_launch(void* const* d_in, const int* in_sizes, int n_in,
                              void* d_out, int out_size) {
    (void)in_sizes; (void)n_in; (void)out_size;
    cudaFuncSetAttribute(mlstm_kernel, cudaFuncAttributeMaxDynamicSharedMemorySize,
                         SMEM_FLOATS * (int)sizeof(float));
    mlstm_kernel<<<64, TPB, SMEM_FLOATS * sizeof(float)>>>(
        (const float*)d_in[0],  (const float*)d_in[1],
        (const float*)d_in[2],  (const float*)d_in[3],
        (const float*)d_in[4],  (const float*)d_in[5],
        (const float*)d_in[6],  (const float*)d_in[7],
        (const float*)d_in[8],
        (const float*)d_in[10], (const float*)d_in[11],
        (const float*)d_in[12], (const float*)d_in[13],
        (const float*)d_in[14], (const float*)d_in[15],
        (float*)d_out);
}

// round 9
// speedup vs baseline: 2.0810x; 1.0456x over previous
#include <cuda_runtime.h>
#include <cooperative_groups.h>

namespace cg = cooperative_groups;

#define CS   8
#define TPB  512

// ---- shared memory layout (float offsets) ----
static constexpr int OFF_WHS  = 0;       // 2*32*129 = 8256 : Whs[bb][q][h] pad129
static constexpr int OFF_WGT  = 8256;    // 256*33 = 8448   : WgT[k][j] pad33 (staging q/p)
static constexpr int OFF_WIHK = 16704;   // 32*520 = 16640  : WihT_k[k][j] (staging Ws/Wt pad132)
static constexpr int OFF_WHHK = 33344;   // 16*520 = 8320   : WhhT_k[k][j]
static constexpr int OFF_WRK  = 41664;   // 16*132 = 2112   : WrT_k[k][j]
static constexpr int OFF_WE   = 43776;   // 128
static constexpr int OFF_WRB  = 43904;   // 128
static constexpr int OFF_WGB  = 44032;   // 32
static constexpr int OFF_BIHH = 44064;   // 64
static constexpr int OFF_MBAR = 44128;   // 16 floats = 8 u64 slots (6 used)
static constexpr int OFF_ST   = 44144;
// per-batch state, stride SBS
static constexpr int P_U    = 0;      // 128
static constexpr int P_X    = 128;    // 256 : [alpha, p_t]
static constexpr int P_PQ   = 384;    // 32
static constexpr int P_XM   = 416;    // 32
static constexpr int P_HM   = 448;    // 16
static constexpr int P_C    = 464;    // 16
static constexpr int P_ACB  = 480;    // 8*128 (pushed)
static constexpr int P_LB   = 1504;   // 8     (pushed)
static constexpr int P_UACB = 1512;   // 8*128 (pushed)
static constexpr int P_GIH  = 2536;   // 8*64  (pushed)
static constexpr int P_GHH  = 3048;   // 2*8*64 parity buffered (pushed)
static constexpr int SBS    = 4072;
static constexpr int SMEM_FLOATS = OFF_ST + 2 * SBS;   // 52288 floats = 209152 B

__device__ __forceinline__ uint32_t MBB(int bb, int i) {   // i: 0 hpart(u), 1 acc, 2 gih+ghh
    return (uint32_t)(OFF_MBAR * 4 + (bb * 3 + i) * 8);
}

__device__ float g_wtp[16 * 128 * 128];   // wt_pre scratch [B][P][H]

__device__ __forceinline__ float fast_tanh(float x) {
    float y; asm("tanh.approx.f32 %0, %1;" : "=f"(y) : "f"(x)); return y;
}
__device__ __forceinline__ float sigm(float x) {
    return __fdividef(1.f, 1.f + __expf(-x));
}
__device__ __forceinline__ float tanh_ex(float x) {
    float e = __expf(2.f * x);
    return 1.f - __fdividef(2.f, e + 1.f);
}
__device__ __forceinline__ float warp_sum(float v) {
    #pragma unroll
    for (int o = 16; o; o >>= 1) v += __shfl_xor_sync(0xffffffffu, v, o);
    return v;
}
__device__ __forceinline__ uint32_t mapa_rank(uint32_t base, int r) {
    uint32_t rm;
    asm("mapa.shared::cluster.u32 %0, %1, %2;" : "=r"(rm) : "r"(base), "r"(r));
    return rm;
}
__device__ __forceinline__ void st_async32(uint32_t rbase, int foff, uint32_t mb_byte, float v) {
    asm volatile("st.async.shared::cluster.mbarrier::complete_tx::bytes.b32 [%0], %1, [%2];"
                 :: "r"(rbase + (uint32_t)foff * 4u), "r"(__float_as_uint(v)),
                    "r"(rbase + mb_byte) : "memory");
}
__device__ __forceinline__ void st_async64(uint32_t rbase, int foff, uint32_t mb_byte,
                                           float a, float b) {
    uint64_t v = ((uint64_t)__float_as_uint(b) << 32) | (uint64_t)__float_as_uint(a);
    asm volatile("st.async.shared::cluster.mbarrier::complete_tx::bytes.b64 [%0], %1, [%2];"
                 :: "r"(rbase + (uint32_t)foff * 4u), "l"(v), "r"(rbase + mb_byte) : "memory");
}
__device__ __forceinline__ void mbar_init(uint32_t addr) {
    asm volatile("mbarrier.init.shared.b64 [%0], 1;" :: "r"(addr) : "memory");
}
__device__ __forceinline__ void mbar_expect(uint32_t addr, uint32_t bytes) {
    asm volatile("mbarrier.arrive.expect_tx.shared.b64 _, [%0], %1;" :: "r"(addr), "r"(bytes) : "memory");
}
__device__ __forceinline__ void mbar_wait(uint32_t addr, uint32_t parity) {
    asm volatile(
        "{\n\t.reg .pred P1;\n\t"
        "WL%=:\n\t"
        "mbarrier.try_wait.parity.acquire.cluster.shared::cta.b64 P1, [%0], %1, 0x989680;\n\t"
        "@P1 bra.uni WD%=;\n\t"
        "bra.uni WL%=;\n\t"
        "WD%=:\n\t}"
        :: "r"(addr), "r"(parity) : "memory");
}
__device__ __forceinline__ void barg(int bb) {
    asm volatile("bar.sync %0, 256;" :: "r"(1 + bb) : "memory");
}
__device__ __forceinline__ void csync() {
    asm volatile("barrier.cluster.arrive.aligned;" ::: "memory");
    asm volatile("barrier.cluster.wait.aligned;" ::: "memory");
}

__global__ void __launch_bounds__(TPB, 1) __cluster_dims__(CS, 1, 1)
mlstm_kernel(const float* __restrict__ p_in,  const float* __restrict__ q_in,
             const float* __restrict__ Ws_w,  const float* __restrict__ Ws_b,
             const float* __restrict__ Wt_w,  const float* __restrict__ Wt_b,
             const float* __restrict__ Wr_w,  const float* __restrict__ Wr_b,
             const float* __restrict__ We_w,
             const float* __restrict__ Wg_w,  const float* __restrict__ Wg_b,
             const float* __restrict__ Wih,   const float* __restrict__ Whh,
             const float* __restrict__ bih,   const float* __restrict__ bhh,
             float* __restrict__ out)
{
    extern __shared__ float s[];
    cg::cluster_group cl = cg::this_cluster();
    const int rank = (int)cl.block_rank();
    const int b0   = (int)(blockIdx.x >> 3) * 2;
    const int tid  = (int)threadIdx.x;
    const int lane = tid & 31;

    // ============================ PROLOGUE ============================
    // P1: Whs[bb] = q(32 rows) @ Ws^T + b  (Ws staged pad132 at OFF_WIHK, q at OFF_WGT)
    for (int i4 = tid; i4 < 4096; i4 += TPB) {
        int hh = i4 >> 5, k = i4 & 31;
        *(float4*)&s[OFF_WIHK + hh * 132 + k * 4] = ((const float4*)Ws_w)[i4];
    }
    #pragma unroll
    for (int bb = 0; bb < 2; bb++)
        for (int i4 = tid; i4 < 1024; i4 += TPB)
            ((float4*)&s[OFF_WGT + bb * 4096])[i4] =
                ((const float4*)(q_in + (size_t)((b0 + bb) * 256 + rank * 32) * 128))[i4];
    __syncthreads();
    #pragma unroll
    for (int bb = 0; bb < 2; bb++) {
        int hh = tid & 127, q0 = (tid >> 7) * 8;
        const float4* wrow = (const float4*)&s[OFF_WIHK + hh * 132];
        float acc[8];
        float sb = Ws_b[hh];
        #pragma unroll
        for (int i = 0; i < 8; i++) acc[i] = sb;
        for (int k = 0; k < 32; k++) {
            float4 w = wrow[k];
            #pragma unroll
            for (int i = 0; i < 8; i++) {
                float4 qv = *(const float4*)&s[OFF_WGT + bb * 4096 + (q0 + i) * 128 + k * 4];
                acc[i] += w.x * qv.x + w.y * qv.y + w.z * qv.z + w.w * qv.w;
            }
        }
        #pragma unroll
        for (int i = 0; i < 8; i++) s[OFF_WHS + bb * 4128 + (q0 + i) * 129 + hh] = acc[i];
    }
    __syncthreads();

    // P2: wt_pre[bb] = p(16 rows) @ Wt^T + b -> gmem scratch
    for (int i4 = tid; i4 < 4096; i4 += TPB) {
        int hh = i4 >> 5, k = i4 & 31;
        *(float4*)&s[OFF_WIHK + hh * 132 + k * 4] = ((const float4*)Wt_w)[i4];
    }
    #pragma unroll
    for (int bb = 0; bb < 2; bb++)
        for (int i4 = tid; i4 < 512; i4 += TPB)
            ((float4*)&s[OFF_WGT + bb * 2048])[i4] =
                ((const float4*)(p_in + (size_t)((b0 + bb) * 128 + rank * 16) * 128))[i4];
    __syncthreads();
    #pragma unroll
    for (int bb = 0; bb < 2; bb++) {
        int hh = tid & 127, t0 = (tid >> 7) * 4;
        const float4* wrow = (const float4*)&s[OFF_WIHK + hh * 132];
        float acc[4];
        float bt = Wt_b[hh];
        #pragma unroll
        for (int i = 0; i < 4; i++) acc[i] = bt;
        for (int k = 0; k < 32; k++) {
            float4 w = wrow[k];
            #pragma unroll
            for (int i = 0; i < 4; i++) {
                float4 pv = *(const float4*)&s[OFF_WGT + bb * 2048 + (t0 + i) * 128 + k * 4];
                acc[i] += w.x * pv.x + w.y * pv.y + w.z * pv.z + w.w * pv.w;
            }
        }
        #pragma unroll
        for (int i = 0; i < 4; i++)
            g_wtp[(size_t)((b0 + bb) * 128 + rank * 16 + t0 + i) * 128 + hh] = acc[i];
    }
    __syncthreads();

    // P3: resident weights (k-partitioned)
    for (int idx = tid; idx < 512 * 32; idx += TPB) {
        int j = idx >> 5, kk = idx & 31;
        s[OFF_WIHK + kk * 520 + j] = Wih[(size_t)j * 256 + rank * 32 + kk];
    }
    for (int idx = tid; idx < 512 * 16; idx += TPB) {
        int j = idx >> 4, kk = idx & 15;
        s[OFF_WHHK + kk * 520 + j] = Whh[(size_t)j * 128 + rank * 16 + kk];
    }
    for (int idx = tid; idx < 128 * 16; idx += TPB) {
        int j = idx >> 4, kk = idx & 15;
        s[OFF_WRK + kk * 132 + j] = Wr_w[(size_t)j * 128 + rank * 16 + kk];
    }
    for (int idx = tid; idx < 8192; idx += TPB) {
        int j = idx >> 8, k = idx & 255;
        s[OFF_WGT + k * 33 + j] = Wg_w[(size_t)(rank * 32 + j) * 256 + k];
    }
    if (tid < 128) { s[OFF_WE + tid] = We_w[tid]; s[OFF_WRB + tid] = Wr_b[tid]; }
    if (tid < 32) s[OFF_WGB + tid] = Wg_b[rank * 32 + tid];
    if (tid < 64) {
        int grow = (tid >> 4) * 128 + rank * 16 + (tid & 15);
        s[OFF_BIHH + tid] = bih[grow] + bhh[grow];
    }
    #pragma unroll
    for (int bbz = 0; bbz < 2; bbz++) {
        int S = OFF_ST + bbz * SBS;
        for (int i = tid; i < 1024; i += TPB) { s[S + P_UACB + i] = 0.f; s[S + P_GHH + i] = 0.f; }
        if (tid < 16) s[S + P_C + tid] = 0.f;
    }
    const uint32_t sbase = (uint32_t)__cvta_generic_to_shared(s);
    if (tid == 0) {
        #pragma unroll
        for (int bbz = 0; bbz < 2; bbz++)
            #pragma unroll
            for (int i = 0; i < 3; i++) mbar_init(sbase + MBB(bbz, i));
        asm volatile("fence.mbarrier_init.release.cluster;" ::: "memory");
        // phase-0 expects: acc 4096+32; gih 2048 (no ghh arrives for step 0)
        #pragma unroll
        for (int bbz = 0; bbz < 2; bbz++) {
            mbar_expect(sbase + MBB(bbz, 1), 4128u);
            mbar_expect(sbase + MBB(bbz, 2), 2048u);
        }
    }
    __threadfence();     // g_wtp visible cluster-wide
    __syncthreads();
    csync();

    // ==================== MAIN LOOP (warp-split batches, 8 warps each) ====================
    const int bb = tid >> 8;           // warps 0-7 -> batch0, 8-15 -> batch1
    const int wg = tid & 255;
    const int cw = wg >> 5;            // chain warp 0..7
    const int S  = OFF_ST + bb * SBS;
    const int gb = b0 + bb;
    uint32_t rb[CS];
    #pragma unroll
    for (int r = 0; r < CS; r++) rb[r] = mapa_rank(sbase, r);
    const uint32_t mb_hp = sbase + MBB(bb, 0);
    const uint32_t mb_ac = sbase + MBB(bb, 1);
    const uint32_t mb_gi = sbase + MBB(bb, 2);
    const uint32_t MB_HP = MBB(bb, 0), MB_AC = MBB(bb, 1), MB_GI = MBB(bb, 2);

    float wtp_r = 0.f, p_r = 0.f;
    if (wg < 128) {
        wtp_r = g_wtp[(size_t)(gb * 128) * 128 + wg];
        p_r   = p_in[(size_t)(gb * 128) * 128 + wg];
    }

    for (int t = 0; t < 128; t++) {
        // ---- A: wait u-partials only (ghh rides mb_gi now); u ----
        if (t) mbar_wait(mb_hp, (t - 1) & 1);
        if (wg == 0) mbar_expect(mb_hp, 4096u);
        if (wg < 128) {
            float u = wtp_r + s[OFF_WRB + wg];
            #pragma unroll
            for (int r = 0; r < CS; r++) u += s[S + P_UACB + r * 128 + wg];
            s[S + P_U + wg] = u;
            s[S + P_X + 128 + wg] = p_r;
        }
        barg(bb);

        // ---- B: scores (cw -> 4 q's) ----
        {
            int q0 = cw * 4;
            const float* whs = &s[OFF_WHS + bb * 4128];
            float a[4] = {0.f, 0.f, 0.f, 0.f};
            #pragma unroll
            for (int c = 0; c < 4; c++) {
                int h = c * 32 + lane;
                float uh = s[S + P_U + h], we = s[OFF_WE + h];
                #pragma unroll
                for (int i = 0; i < 4; i++)
                    a[i] += fast_tanh(whs[(q0 + i) * 129 + h] + uh) * we;
            }
            #pragma unroll
            for (int i = 0; i < 4; i++) a[i] = warp_sum(a[i]);
            if (lane == 0) {   // no-max softmax: |score| <= ||We||_1 ~ 5
                #pragma unroll
                for (int i = 0; i < 4; i++) s[S + P_PQ + q0 + i] = __expf(a[i]);
            }
        }
        barg(bb);

        // ---- push acc (b64-paired, rank-rotated) + l ----
        if (wg < 128) {
            float a = 0.f;
            #pragma unroll
            for (int q = 0; q < 32; q++)
                a += s[S + P_PQ + q] * s[OFF_WHS + bb * 4128 + q * 129 + wg];
            float an = __shfl_xor_sync(0xffffffffu, a, 1);
            if (!(wg & 1)) {
                #pragma unroll
                for (int i = 0; i < CS; i++) {
                    int r = (rank + 1 + i) & 7;
                    st_async64(rb[r], S + P_ACB + rank * 128 + wg, MB_AC, a, an);
                }
            }
        } else if (cw == 4) {
            float l = warp_sum(s[S + P_PQ + lane]);
            if (lane == 0) {
                #pragma unroll
                for (int i = 0; i < CS; i++) {
                    int r = (rank + 1 + i) & 7;
                    st_async32(rb[r], S + P_LB + rank, MB_AC, l);
                }
            }
        }

        // ---- D_p: p-half of input gate (overlaps exch1 delivery) ----
        float dp[4];
        {
            int j0 = cw * 4;
            #pragma unroll
            for (int i = 0; i < 4; i++) dp[i] = 0.f;
            #pragma unroll
            for (int c = 4; c < 8; c++) {
                int k = c * 32 + lane;
                float xv = s[S + P_X + k];
                #pragma unroll
                for (int i = 0; i < 4; i++)
                    dp[i] += s[OFF_WGT + k * 33 + j0 + i] * xv;
            }
        }

        // ---- C: wait acc; alpha ----
        mbar_wait(mb_ac, t & 1);
        if (wg == 0) mbar_expect(mb_ac, 4128u);
        if (wg < 128) {
            float a = 0.f, L = 0.f;
            #pragma unroll
            for (int r = 0; r < CS; r++) {
                a += s[S + P_ACB + r * 128 + wg];
                L += s[S + P_LB + r];
            }
            s[S + P_X + wg] = __fdividef(a, L);
        }
        barg(bb);

        // ---- D_alpha: alpha-half; finish gate ----
        {
            int j0 = cw * 4;
            float a[4] = {dp[0], dp[1], dp[2], dp[3]};
            #pragma unroll
            for (int c = 0; c < 4; c++) {
                int k = c * 32 + lane;
                float xv = s[S + P_X + k];
                #pragma unroll
                for (int i = 0; i < 4; i++)
                    a[i] += s[OFF_WGT + k * 33 + j0 + i] * xv;
            }
            #pragma unroll
            for (int i = 0; i < 4; i++) a[i] = warp_sum(a[i]);
            if (lane == 0) {
                #pragma unroll
                for (int i = 0; i < 4; i++) {
                    float g = sigm(a[i] + s[OFF_WGB + j0 + i]);
                    s[S + P_XM + j0 + i] = g * s[S + P_X + rank * 32 + j0 + i];
                }
            }
        }
        barg(bb);

        // ---- Dfin: Wih k-partial gates (2 consecutive j per thread, b64 push) ----
        {
            int j = 2 * wg;                     // 0..510
            float a0 = 0.f, a1 = 0.f;
            #pragma unroll
            for (int k = 0; k < 32; k++) {
                float xm = s[S + P_XM + k];
                float2 w2 = *(const float2*)&s[OFF_WIHK + k * 520 + j];
                a0 += w2.x * xm; a1 += w2.y * xm;
            }
            int hh = j & 127;
            int owner = hh >> 4;
            int slot = (j >> 7) * 16 + (hh & 15);
            st_async64(rb[owner], S + P_GIH + rank * 64 + slot, MB_GI, a0, a1);
        }

        // prefetch next step's wtp / p
        if (wg < 128) {
            int tn = (t < 127) ? t + 1 : 127;
            wtp_r = g_wtp[(size_t)(gb * 128 + tn) * 128 + wg];
            p_r   = p_in[(size_t)(gb * 128 + tn) * 128 + wg];
        }

        // ---- F: wait gih(t) [+ ghh(t), pushed at end of t-1]; pointwise ----
        mbar_wait(mb_gi, t & 1);
        if (wg == 0) mbar_expect(mb_gi, 4096u);   // next phase: gih 2048 + ghh 2048
        if (wg < 16) {
            float g[4];
            #pragma unroll
            for (int gt = 0; gt < 4; gt++) {
                float v = s[OFF_BIHH + gt * 16 + wg];
                #pragma unroll
                for (int r = 0; r < CS; r++) {
                    v += s[S + P_GIH + r * 64 + gt * 16 + wg];
                    v += s[S + P_GHH + (t & 1) * 512 + r * 64 + gt * 16 + wg];
                }
                g[gt] = v;
            }
            float cn = sigm(g[1]) * s[S + P_C + wg] + sigm(g[0]) * tanh_ex(g[2]);
            float hn = sigm(g[3]) * tanh_ex(cn);
            s[S + P_C + wg]  = cn;
            s[S + P_HM + wg] = hn;
            out[(size_t)(gb * 128 + t) * 128 + rank * 16 + wg] = hn;
        }
        barg(bb);

        // ---- push h-partials: u-parts -> mb_hp ; Whh gate-parts -> mb_gi(t+1) ----
        if (t < 127) {
            if (wg < 128) {
                float pu = 0.f;
                #pragma unroll
                for (int k = 0; k < 16; k++)
                    pu += s[OFF_WRK + k * 132 + wg] * s[S + P_HM + k];
                float pn = __shfl_xor_sync(0xffffffffu, pu, 1);
                if (!(wg & 1)) {
                    #pragma unroll
                    for (int i = 0; i < CS; i++) {
                        int r = (rank + 1 + i) & 7;
                        st_async64(rb[r], S + P_UACB + rank * 128 + wg, MB_HP, pu, pn);
                    }
                }
            }
            {
                int j = 2 * wg;
                float a0 = 0.f, a1 = 0.f;
                #pragma unroll
                for (int k = 0; k < 16; k++) {
                    float hv = s[S + P_HM + k];
                    float2 w2 = *(const float2*)&s[OFF_WHHK + k * 520 + j];
                    a0 += w2.x * hv; a1 += w2.y * hv;
                }
                int hh = j & 127;
                int owner = hh >> 4;
                int slot = (j >> 7) * 16 + (hh & 15);
                st_async64(rb[owner],
                           S + P_GHH + ((t + 1) & 1) * 512 + rank * 64 + slot, MB_GI, a0, a1);
            }
        }
    }

    csync();   // no CTA exits while peers may still target its SMEM
}

extern "C" void kernel_launch(void* const* d_in, const int* in_sizes, int n_in,
                              void* d_out, int out_size) {
    (void)in_sizes; (void)n_in; (void)out_size;
    cudaFuncSetAttribute(mlstm_kernel, cudaFuncAttributeMaxDynamicSharedMemorySize,
                         SMEM_FLOATS * (int)sizeof(float));
    mlstm_kernel<<<64, TPB, SMEM_FLOATS * sizeof(float)>>>(
        (const float*)d_in[0],  (const float*)d_in[1],
        (const float*)d_in[2],  (const float*)d_in[3],
        (const float*)d_in[4],  (const float*)d_in[5],
        (const float*)d_in[6],  (const float*)d_in[7],
        (const float*)d_in[8],
        (const float*)d_in[10], (const float*)d_in[11],
        (const float*)d_in[12], (const float*)d_in[13],
        (const float*)d_in[14], (const float*)d_in[15],
        (float*)d_out);
}